// round 2
// baseline (speedup 1.0000x reference)
#include <cuda_runtime.h>

#define NB    64      // batch = grid
#define PW    68      // 64 + 2*2 halo
#define BUF   4624    // 68*68
#define NPIX  4096    // 64*64
#define NTH   512

// Prep outputs (device-global scratch: no allocation allowed)
__device__ float g_T[104];   // T[tap][z], z in 0..3 (3 = zero-pad sentinel)
__device__ float g_effb;

// ---------------------------------------------------------------------------
// Prep: collapse encode_w (150x2x5x5) + r_w (1x150x1x1) + emb (3x2) into a
// 25-tap x 3-symbol lookup table T and scalar bias eff_b.
// ---------------------------------------------------------------------------
__global__ void prep_kernel(const float* __restrict__ emb,
                            const float* __restrict__ encode_w,
                            const float* __restrict__ encode_b,
                            const float* __restrict__ r_w) {
    __shared__ float effw[50];
    int t = threadIdx.x;
    if (t < 50) {
        float s = 0.f;
        for (int c = 0; c < 150; ++c) s = fmaf(r_w[c], encode_w[c * 50 + t], s);
        effw[t] = s;
    }
    __syncthreads();
    if (t < 25) {
        float w0 = effw[t], w1 = effw[25 + t];
        #pragma unroll
        for (int z = 0; z < 3; ++z)
            g_T[t * 4 + z] = w0 * emb[2 * z] + w1 * emb[2 * z + 1];
        g_T[t * 4 + 3] = 0.f;   // padding symbol
    } else if (t == 32) {
        float s = 0.f;
        for (int c = 0; c < 150; ++c) s = fmaf(r_w[c], encode_b[c], s);
        g_effb = s;
    }
}

// ---------------------------------------------------------------------------
// Main fused VIN kernel: one CTA per batch image, everything in SMEM.
// Thread layout: 512 threads, each owns an 8-row column strip (x = tid&63,
// y0 = (tid>>6)*8) -> all SMEM accesses are lane-stride-1 (conflict-free).
// ---------------------------------------------------------------------------
__global__ __launch_bounds__(NTH, 1)
void vin_kernel(const int* __restrict__ maze,
                const float* __restrict__ q_w,
                const float* __restrict__ w_in,
                const float* __restrict__ fc_w,
                float* __restrict__ out) {
    extern __shared__ float sm[];
    float* bufA = sm;                  // v ping (zero halo)
    float* bufB = sm + BUF;            // v pong (doubles as maze tile in setup)
    float* r_s  = sm + 2 * BUF;        // r with zero halo
    float* Rq_s = sm + 3 * BUF;        // [8][4096] iteration-invariant conv(r, q_w)
    float* T_s  = Rq_s + 8 * NPIX;     // 104
    float* qw_s = T_s + 104;           // 200
    float* w_s  = qw_s + 200;          // 200
    float* fc_s = w_s + 200;           // 32

    const int tid = threadIdx.x;
    const int b   = blockIdx.x;
    const int x   = tid & 63;
    const int ys  = (tid >> 6) << 3;   // first output row of this strip

    int* m_tile = (int*)bufB;

    // --- init: zero halos, pad maze tile with sentinel 3, stage coefficients
    for (int i = tid; i < BUF; i += NTH) { bufA[i] = 0.f; r_s[i] = 0.f; m_tile[i] = 3; }
    for (int i = tid; i < 200; i += NTH) { qw_s[i] = q_w[i]; w_s[i] = w_in[i]; }
    if (tid < 104) T_s[tid] = g_T[tid];
    if (tid < 32)  fc_s[tid] = fc_w[tid];
    __syncthreads();

    const int* mz = maze + b * NPIX;
    for (int i = tid; i < NPIX; i += NTH)
        m_tile[((i >> 6) + 2) * PW + (i & 63) + 2] = mz[i];
    __syncthreads();

    // --- phase 1: r = eff_b + sum_tap T[tap][maze(window)]
    {
        int mwin[12][5];
        #pragma unroll
        for (int dy = 0; dy < 12; ++dy)
            #pragma unroll
            for (int dx = 0; dx < 5; ++dx)
                mwin[dy][dx] = m_tile[(ys + dy) * PW + x + dx];
        float eb = g_effb;
        float racc[8];
        #pragma unroll
        for (int j = 0; j < 8; ++j) racc[j] = eb;
        #pragma unroll
        for (int ky = 0; ky < 5; ++ky)
            #pragma unroll
            for (int kx = 0; kx < 5; ++kx) {
                const float* Tr = T_s + (ky * 5 + kx) * 4;
                #pragma unroll
                for (int j = 0; j < 8; ++j)
                    racc[j] += Tr[mwin[j + ky][kx]];
            }
        #pragma unroll
        for (int j = 0; j < 8; ++j)
            r_s[(ys + j + 2) * PW + x + 2] = racc[j];
    }
    __syncthreads();

    // --- phase 2: Rq = conv(r, q_w) (kept in SMEM), v1 = max_a Rq; re-zero bufB
    {
        float rwin[12][5];
        #pragma unroll
        for (int dy = 0; dy < 12; ++dy)
            #pragma unroll
            for (int dx = 0; dx < 5; ++dx)
                rwin[dy][dx] = r_s[(ys + dy) * PW + x + dx];
        float vmax[8];
        #pragma unroll
        for (int a = 0; a < 8; ++a) {
            float acc[8] = {0.f,0.f,0.f,0.f,0.f,0.f,0.f,0.f};
            #pragma unroll
            for (int ky = 0; ky < 5; ++ky)
                #pragma unroll
                for (int kx = 0; kx < 5; ++kx) {
                    float c = qw_s[a * 25 + ky * 5 + kx];
                    #pragma unroll
                    for (int j = 0; j < 8; ++j)
                        acc[j] = fmaf(c, rwin[j + ky][kx], acc[j]);
                }
            #pragma unroll
            for (int j = 0; j < 8; ++j) {
                Rq_s[a * NPIX + (ys + j) * 64 + x] = acc[j];
                vmax[j] = (a == 0) ? acc[j] : fmaxf(vmax[j], acc[j]);
            }
        }
        #pragma unroll
        for (int j = 0; j < 8; ++j)
            bufA[(ys + j + 2) * PW + x + 2] = vmax[j];
        for (int i = tid; i < BUF; i += NTH) bufB[i] = 0.f;  // clear maze sentinels
    }
    __syncthreads();

    // --- K-1 = 9 value-iteration steps producing v; Rq stays resident
    float* vin  = bufA;
    float* vout = bufB;
    for (int t = 0; t < 9; ++t) {
        float vw[12][5];
        #pragma unroll
        for (int dy = 0; dy < 12; ++dy)
            #pragma unroll
            for (int dx = 0; dx < 5; ++dx)
                vw[dy][dx] = vin[(ys + dy) * PW + x + dx];
        float vmax[8];
        #pragma unroll
        for (int a = 0; a < 8; ++a) {
            float acc[8] = {0.f,0.f,0.f,0.f,0.f,0.f,0.f,0.f};
            #pragma unroll
            for (int ky = 0; ky < 5; ++ky)
                #pragma unroll
                for (int kx = 0; kx < 5; ++kx) {
                    float c = w_s[a * 25 + ky * 5 + kx];
                    #pragma unroll
                    for (int j = 0; j < 8; ++j)
                        acc[j] = fmaf(c, vw[j + ky][kx], acc[j]);
                }
            #pragma unroll
            for (int j = 0; j < 8; ++j) {
                float qa = acc[j] + Rq_s[a * NPIX + (ys + j) * 64 + x];
                vmax[j] = (a == 0) ? qa : fmaxf(vmax[j], qa);
            }
        }
        #pragma unroll
        for (int j = 0; j < 8; ++j)
            vout[(ys + j + 2) * PW + x + 2] = vmax[j];
        __syncthreads();
        float* tmp = vin; vin = vout; vout = tmp;
    }

    // --- final step: q10 = Rq + conv(v10, w), folded directly into fc matvec
    {
        float vw[12][5];
        #pragma unroll
        for (int dy = 0; dy < 12; ++dy)
            #pragma unroll
            for (int dx = 0; dx < 5; ++dx)
                vw[dy][dx] = vin[(ys + dy) * PW + x + dx];
        float o0[8], o1[8], o2[8], o3[8];
        #pragma unroll
        for (int j = 0; j < 8; ++j) { o0[j]=0.f; o1[j]=0.f; o2[j]=0.f; o3[j]=0.f; }
        #pragma unroll
        for (int a = 0; a < 8; ++a) {
            float acc[8] = {0.f,0.f,0.f,0.f,0.f,0.f,0.f,0.f};
            #pragma unroll
            for (int ky = 0; ky < 5; ++ky)
                #pragma unroll
                for (int kx = 0; kx < 5; ++kx) {
                    float c = w_s[a * 25 + ky * 5 + kx];
                    #pragma unroll
                    for (int j = 0; j < 8; ++j)
                        acc[j] = fmaf(c, vw[j + ky][kx], acc[j]);
                }
            float f0 = fc_s[a], f1 = fc_s[8 + a], f2 = fc_s[16 + a], f3 = fc_s[24 + a];
            #pragma unroll
            for (int j = 0; j < 8; ++j) {
                float qa = acc[j] + Rq_s[a * NPIX + (ys + j) * 64 + x];
                o0[j] = fmaf(f0, qa, o0[j]);
                o1[j] = fmaf(f1, qa, o1[j]);
                o2[j] = fmaf(f2, qa, o2[j]);
                o3[j] = fmaf(f3, qa, o3[j]);
            }
        }
        float4* op = (float4*)(out + (size_t)b * NPIX * 4);
        #pragma unroll
        for (int j = 0; j < 8; ++j)
            op[(ys + j) * 64 + x] = make_float4(o0[j], o1[j], o2[j], o3[j]);
    }
}

// ---------------------------------------------------------------------------
extern "C" void kernel_launch(void* const* d_in, const int* in_sizes, int n_in,
                              void* d_out, int out_size) {
    const int*   maze     = (const int*)d_in[0];
    const float* emb      = (const float*)d_in[1];
    const float* encode_w = (const float*)d_in[2];
    const float* encode_b = (const float*)d_in[3];
    const float* r_w      = (const float*)d_in[4];
    const float* q_w      = (const float*)d_in[5];
    const float* w_in     = (const float*)d_in[6];
    const float* fc_w     = (const float*)d_in[7];
    float* out = (float*)d_out;

    prep_kernel<<<1, 64>>>(emb, encode_w, encode_b, r_w);

    const int smem_bytes = (3 * BUF + 8 * NPIX + 104 + 200 + 200 + 32) * (int)sizeof(float);
    cudaFuncSetAttribute(vin_kernel,
                         cudaFuncAttributeMaxDynamicSharedMemorySize, smem_bytes);
    vin_kernel<<<NB, NTH, smem_bytes>>>(maze, q_w, w_in, fc_w, out);
}